// round 17
// baseline (speedup 1.0000x reference)
#include <cuda_runtime.h>
#include <float.h>
#include <math.h>

// ---------------------------------------------------------------------------
// Problem constants
// ---------------------------------------------------------------------------
#define BB    8
#define NN    2048
#define KNNK  20
#define CIN   67          // 3 xyz + 64 feat
#define CFE   64
#define CCC   144         // 64 gpn + 64 center + 16 pos
#define CR    80
#define CH    64
#define DIMV  16
#define DIMK  32
#define NHEAD 8
#define COUT  128
#define EPSF  1e-5f
#define XYZ_TOT (BB*NN*3)
#define GPW   128         // padded per-point transform row in GLOBAL (floats)
#define GPS   112         // per-point transform row in SHARED (floats)
#define GP_G1 0
#define GP_GV 64
#define GP_GK 80

typedef unsigned long long ull;

// scratch (no allocation allowed -> __device__ globals)
__device__ int    g_idx[BB * NN * KNNK];
__device__ float4 W1gp[(CR/4) * CH];            // [c4 0..19][o]  (c4<16: feat, >=16: pos)
__device__ float4 W1dp[(CFE/4) * CH];           // center-fold diff for W1
__device__ float4 W2p [(CH/4)  * CH];
__device__ float4 Wqp [(CH/4)  * (NHEAD*DIMK)];
__device__ float4 Wvgp[(CR/4) * DIMV];
__device__ float4 Wvdp[(CFE/4) * DIMV];
__device__ float4 Wkgp[(CR/4) * DIMK];
__device__ float4 g_GP4[BB * NN * (GPW/4)];     // padded per-point feat transforms
__device__ float  g_C1V[BB * NN * 80];          // per-point center-fold consts
__device__ float4 g_XYZS[BB * NN];              // packed (x, y, z, |p|^2)

// ---------------------------------------------------------------------------
// packed dual-fp32 FMA helpers
// ---------------------------------------------------------------------------
__device__ __forceinline__ void ffma2(ull& d, ull a, ull b)
{
    asm("fma.rn.f32x2 %0, %1, %2, %0;" : "+l"(d) : "l"(a), "l"(b));
}
__device__ __forceinline__ float hsum2(ull v)
{
    float lo, hi;
    asm("mov.b64 {%0, %1}, %2;" : "=f"(lo), "=f"(hi) : "l"(v));
    return lo + hi;
}
__device__ __forceinline__ ulonglong2 ldp(const void* p)
{
    return *(const ulonglong2*)p;
}

// ---------------------------------------------------------------------------
// Kernel 0: pack weights (transposed + center-folded layouts)
// ---------------------------------------------------------------------------
__global__ void pack_weights(const float* __restrict__ W1, const float* __restrict__ W2,
                             const float* __restrict__ Wq, const float* __restrict__ Wv,
                             const float* __restrict__ Wk)
{
    int i = blockIdx.x * blockDim.x + threadIdx.x;

    if (i < (CR/4)*CH) {
        int c4 = i >> 6, o = i & 63;
        int col = (c4 < 16) ? 4 * c4 : 128 + 4 * (c4 - 16);
        W1gp[i] = *(const float4*)&W1[o * CCC + col];
        return;
    }
    i -= (CR/4)*CH;
    if (i < (CFE/4)*CH) {
        int c4 = i >> 6, o = i & 63;
        float4 a = *(const float4*)&W1[o * CCC + 64 + 4 * c4];
        float4 b = *(const float4*)&W1[o * CCC + 4 * c4];
        W1dp[i] = make_float4(a.x - b.x, a.y - b.y, a.z - b.z, a.w - b.w);
        return;
    }
    i -= (CFE/4)*CH;
    if (i < (CH/4)*CH) {
        int c4 = i >> 6, o = i & 63;
        W2p[i] = *(const float4*)&W2[o * CH + 4 * c4];
        return;
    }
    i -= (CH/4)*CH;
    if (i < (CH/4)*NHEAD*DIMK) {
        int c4 = i >> 8, o = i & 255;
        Wqp[i] = *(const float4*)&Wq[o * CH + 4 * c4];
        return;
    }
    i -= (CH/4)*NHEAD*DIMK;
    if (i < (CR/4)*DIMV) {
        int c4 = i >> 4, vd = i & 15;
        int col = (c4 < 16) ? 4 * c4 : 128 + 4 * (c4 - 16);
        Wvgp[i] = *(const float4*)&Wv[vd * CCC + col];
        return;
    }
    i -= (CR/4)*DIMV;
    if (i < (CFE/4)*DIMV) {
        int c4 = i >> 4, vd = i & 15;
        float4 a = *(const float4*)&Wv[vd * CCC + 64 + 4 * c4];
        float4 b = *(const float4*)&Wv[vd * CCC + 4 * c4];
        Wvdp[i] = make_float4(a.x - b.x, a.y - b.y, a.z - b.z, a.w - b.w);
        return;
    }
    i -= (CFE/4)*DIMV;
    if (i < (CR/4)*DIMK) {
        int c4 = i >> 5, d = i & 31;
        int col = (c4 < 16) ? 4 * c4 : 128 + 4 * (c4 - 16);
        Wkgp[i] = *(const float4*)&Wk[d * CCC + col];
    }
}

// ---------------------------------------------------------------------------
// Kernel 0b: per-point precompute.
// ---------------------------------------------------------------------------
__global__ void __launch_bounds__(128)
precompute_points(const float* __restrict__ x)
{
    const int pt = blockIdx.x;
    const int t  = threadIdx.x;
    __shared__ __align__(16) float sf[CFE];

    const float* xc = x + (size_t)pt * CIN;
    if (t < CFE) sf[t] = xc[3 + t];
    __syncthreads();

    float* gp = (float*)g_GP4 + (size_t)pt * GPW;

    if (t < 112) {
        ull a = 0ull;
        if (t < GP_GV) {
            #pragma unroll
            for (int c4 = 0; c4 < 16; c4++) {
                const ulonglong2 w = ldp(&W1gp[c4 * CH + t]);
                const ulonglong2 f = ldp(&sf[4 * c4]);
                ffma2(a, w.x, f.x);
                ffma2(a, w.y, f.y);
            }
        } else if (t < GP_GK) {
            const int vd = t - GP_GV;
            #pragma unroll
            for (int c4 = 0; c4 < 16; c4++) {
                const ulonglong2 w = ldp(&Wvgp[c4 * DIMV + vd]);
                const ulonglong2 f = ldp(&sf[4 * c4]);
                ffma2(a, w.x, f.x);
                ffma2(a, w.y, f.y);
            }
        } else {
            const int d = t - GP_GK;
            #pragma unroll
            for (int c4 = 0; c4 < 16; c4++) {
                const ulonglong2 w = ldp(&Wkgp[c4 * DIMK + d]);
                const ulonglong2 f = ldp(&sf[4 * c4]);
                ffma2(a, w.x, f.x);
                ffma2(a, w.y, f.y);
            }
        }
        gp[t] = hsum2(a);
    } else {
        gp[t] = 0.f;   // pad
        if (t == 127) {
            const float a0 = xc[0], a1 = xc[1], a2 = xc[2];
            g_XYZS[pt] = make_float4(a0, a1, a2, a0 * a0 + a1 * a1 + a2 * a2);
        }
    }

    // pass 2: center-fold constants
    if (t < CFE) {
        ull a = 0ull;
        #pragma unroll
        for (int c4 = 0; c4 < 16; c4++) {
            const ulonglong2 w = ldp(&W1dp[c4 * CH + t]);
            const ulonglong2 f = ldp(&sf[4 * c4]);
            ffma2(a, w.x, f.x);
            ffma2(a, w.y, f.y);
        }
        g_C1V[(size_t)pt * 80 + t] = hsum2(a);
    } else if (t < 80) {
        const int vd = t - CFE;
        ull a = 0ull;
        #pragma unroll
        for (int c4 = 0; c4 < 16; c4++) {
            const ulonglong2 w = ldp(&Wvdp[c4 * DIMV + vd]);
            const ulonglong2 f = ldp(&sf[4 * c4]);
            ffma2(a, w.x, f.x);
            ffma2(a, w.y, f.y);
        }
        g_C1V[(size_t)pt * 80 + t] = hsum2(a);
    }
}

// ---------------------------------------------------------------------------
// Kernel 1: KNN, no distance array. Per-lane top-3 cache + consumed bitmask;
// rescans recompute distances (identical expression -> identical values).
// ---------------------------------------------------------------------------
__global__ void knn_kernel()
{
    extern __shared__ float sm[];
    float4* sP = (float4*)sm;          // [NN] packed (x,y,z,ss) = 32 KB

    const int b     = blockIdx.x >> 8;
    const int qbase = (blockIdx.x & 255) << 3;
    const int t     = threadIdx.x;
    const int w     = t >> 5;
    const int lane  = t & 31;

    for (int j = t; j < NN; j += 256)
        sP[j] = g_XYZS[b * NN + j];
    __syncthreads();

    const int n = qbase + w;
    const float4 q4 = sP[n];

    float v1 = FLT_MAX, v2 = FLT_MAX, v3 = FLT_MAX;
    int   i1 = 0x7fffffff, i2 = 0x7fffffff, i3 = 0x7fffffff;
    ull consumed = 0ull;

    #pragma unroll 4
    for (int s = 0; s < NN / 32; s++) {
        const int j = lane + (s << 5);
        const float4 v = sP[j];
        const float dot = q4.x * v.x + q4.y * v.y + q4.z * v.z;
        const float d   = -2.0f * dot + q4.w + v.w;
        if (d < v1)      { v3 = v2; i3 = i2; v2 = v1; i2 = i1; v1 = d; i1 = j; }
        else if (d < v2) { v3 = v2; i3 = i2; v2 = d;  i2 = j; }
        else if (d < v3) { v3 = d;  i3 = j; }
    }

    for (int sel = 0; sel < KNNK; sel++) {
        float wv = v1;
        int   wi = i1;
        #pragma unroll
        for (int o = 16; o; o >>= 1) {
            float ov = __shfl_xor_sync(0xffffffffu, wv, o);
            int   oi = __shfl_xor_sync(0xffffffffu, wi, o);
            if (ov < wv || (ov == wv && oi < wi)) { wv = ov; wi = oi; }
        }
        if (lane == 0)
            g_idx[((size_t)b * NN + n) * KNNK + sel] = wi;
        if (i1 == wi) {                          // owner lane (indices unique)
            consumed |= 1ull << (wi >> 5);
            v1 = v2; i1 = i2;
            v2 = v3; i2 = i3;
            v3 = FLT_MAX; i3 = 0x7fffffff;
            if (v1 == FLT_MAX) {                 // cache empty -> rescan stripe
                for (int s = 0; s < NN / 32; s++) {
                    if ((consumed >> s) & 1ull) continue;
                    const int j = lane + (s << 5);
                    const float4 v = sP[j];
                    const float dot = q4.x * v.x + q4.y * v.y + q4.z * v.z;
                    const float d   = -2.0f * dot + q4.w + v.w;
                    if (d < v1)      { v3 = v2; i3 = i2; v2 = v1; i2 = i1; v1 = d; i1 = j; }
                    else if (d < v2) { v3 = v2; i3 = i2; v2 = d;  i2 = j; }
                    else if (d < v3) { v3 = d;  i3 = j; }
                }
            }
        }
    }
}

// ---------------------------------------------------------------------------
// fused block reduction: component-wise sum of float4 over 128 threads
// ---------------------------------------------------------------------------
__device__ __forceinline__ float4 block_sum4_128(float4 v, float4* sred, float4* sbc)
{
    #pragma unroll
    for (int o = 16; o; o >>= 1) {
        v.x += __shfl_xor_sync(0xffffffffu, v.x, o);
        v.y += __shfl_xor_sync(0xffffffffu, v.y, o);
        v.z += __shfl_xor_sync(0xffffffffu, v.z, o);
        v.w += __shfl_xor_sync(0xffffffffu, v.w, o);
    }
    if ((threadIdx.x & 31) == 0) sred[threadIdx.x >> 5] = v;
    __syncthreads();
    if (threadIdx.x == 0) {
        float4 a = sred[0], b = sred[1], c = sred[2], d = sred[3];
        *sbc = make_float4(a.x + b.x + c.x + d.x, a.y + b.y + c.y + d.y,
                           a.z + b.z + c.z + d.z, a.w + b.w + c.w + d.w);
    }
    __syncthreads();
    return *sbc;
}

// ---------------------------------------------------------------------------
// Kernel 2: fused block, TWO points per block, o-paired GEMM mapping.
// ---------------------------------------------------------------------------
__global__ void __launch_bounds__(128)
fused_kernel(const float* __restrict__ Wh,
             const float* __restrict__ g1, const float* __restrict__ b1,
             const float* __restrict__ g2, const float* __restrict__ b2,
             const float* __restrict__ lnqw, const float* __restrict__ lnqb,
             const float* __restrict__ lnvw, const float* __restrict__ lnvb,
             const float* __restrict__ lnow, const float* __restrict__ lnob,
             float* __restrict__ out)
{
    const int bn0 = blockIdx.x << 1;
    const int b   = bn0 >> 11;
    const int n0  = bn0 & (NN - 1);
    const int t   = threadIdx.x;

    __shared__ __align__(16) float sGP [2][KNNK * GPS];   // 2 x 20 x 112
    __shared__ __align__(16) float sPos[2][KNNK * DIMV];
    __shared__ __align__(16) float sH1[2][KNNK * CH];
    __shared__ __align__(16) float sPM[2][4 * CH];
    __shared__ __align__(16) float sFQ[2][CH];
    __shared__ __align__(16) float sQ [2][NHEAD * DIMK];
    __shared__ __align__(16) float sV [2][KNNK * DIMV];
    __shared__ __align__(16) float sKK[2][KNNK * DIMK];
    __shared__ __align__(16) float sKVT[2][DIMV * DIMK];  // transposed kv
    __shared__ int    sIdx[2][KNNK];
    __shared__ float4 sred[4];
    __shared__ float4 sbc[1];

    if (t < 2 * KNNK) {
        const int p = t / KNNK, kk = t - p * KNNK;
        sIdx[p][kk] = g_idx[(size_t)(bn0 + p) * KNNK + kk];
    }
    if (t < 6) {   // xyz passthrough
        const int p = t / 3, c = t - 3 * p;
        out[(size_t)(bn0 + p) * 3 + c] = ((const float*)&g_XYZS[bn0 + p])[c];
    }
    __syncthreads();

    // ---- gather per-neighbor transforms (28 aligned float4 per neighbor) -------
    #pragma unroll
    for (int p = 0; p < 2; p++) {
        for (int i = t; i < KNNK * (GPS / 4); i += 128) {
            const int k = i / (GPS / 4), q = i - k * (GPS / 4);
            ((float4*)sGP[p])[i] =
                g_GP4[(size_t)(b * NN + sIdx[p][k]) * (GPW / 4) + q];
        }
    }

    // ---- pos features from packed xyz -------------------------------------------
    {
        const float4 cen0 = g_XYZS[bn0];
        const float4 cen1 = g_XYZS[bn0 + 1];
        #pragma unroll
        for (int p = 0; p < 2; p++) {
            const float cx = p ? cen1.x : cen0.x;
            const float cy = p ? cen1.y : cen0.y;
            const float cz = p ? cen1.z : cen0.z;
            for (int i = t; i < KNNK * DIMV; i += 128) {
                const int k = i >> 4, vd = i & 15;
                const float4 nb = g_XYZS[b * NN + sIdx[p][k]];
                const float rx = nb.x - cx, ry = nb.y - cy, rz = nb.z - cz;
                sPos[p][i] =
                    Wh[vd * 3 + 0] * rx + Wh[vd * 3 + 1] * ry + Wh[vd * 3 + 2] * rz;
            }
        }
    }
    __syncthreads();

    const float bn_rs = rsqrtf(1.0f + EPSF);
    const int o1 = t & 31;
    const int o2 = o1 + 32;
    const int wg = t >> 5;            // warp owns rows k = wg + 4j

    // ---- GEMM1 (pos-only 16ch) + gathered feat + C1; o-paired -------------------
    {
        ull acc[2][5][2];
        #pragma unroll
        for (int oi = 0; oi < 2; oi++)
            #pragma unroll
            for (int j = 0; j < 5; j++) { acc[oi][j][0] = 0ull; acc[oi][j][1] = 0ull; }
        #pragma unroll
        for (int c4 = 0; c4 < 4; c4++) {
            const ulonglong2 w1 = ldp(&W1gp[(16 + c4) * CH + o1]);
            const ulonglong2 w2 = ldp(&W1gp[(16 + c4) * CH + o2]);
            #pragma unroll
            for (int j = 0; j < 5; j++) {
                #pragma unroll
                for (int p = 0; p < 2; p++) {
                    const ulonglong2 f = ldp(&sPos[p][(wg + 4 * j) * DIMV + 4 * c4]);
                    ffma2(acc[0][j][p], w1.x, f.x);  ffma2(acc[0][j][p], w1.y, f.y);
                    ffma2(acc[1][j][p], w2.x, f.x);  ffma2(acc[1][j][p], w2.y, f.y);
                }
            }
        }
        const float c1a0 = g_C1V[(size_t)bn0 * 80 + o1];
        const float c1b0 = g_C1V[(size_t)bn0 * 80 + o2];
        const float c1a1 = g_C1V[(size_t)(bn0 + 1) * 80 + o1];
        const float c1b1 = g_C1V[(size_t)(bn0 + 1) * 80 + o2];
        const float sca = g1[o1] * bn_rs, boa = b1[o1];
        const float scb = g1[o2] * bn_rs, bob = b1[o2];
        #pragma unroll
        for (int j = 0; j < 5; j++) {
            const int k = wg + 4 * j;
            #pragma unroll
            for (int p = 0; p < 2; p++) {
                const float ha = hsum2(acc[0][j][p]) + sGP[p][k * GPS + GP_G1 + o1]
                               + (p ? c1a1 : c1a0);
                const float hb = hsum2(acc[1][j][p]) + sGP[p][k * GPS + GP_G1 + o2]
                               + (p ? c1b1 : c1b0);
                sH1[p][k * CH + o1] = fmaxf(ha * sca + boa, 0.f);
                sH1[p][k * CH + o2] = fmaxf(hb * scb + bob, 0.f);
            }
        }
    }
    __syncwarp();   // GEMM1->GEMM2 is warp-private under this mapping

    // ---- GEMM2 + fold relu/max over k; o-paired ----------------------------------
    {
        ull acc[2][5][2];
        #pragma unroll
        for (int oi = 0; oi < 2; oi++)
            #pragma unroll
            for (int j = 0; j < 5; j++) { acc[oi][j][0] = 0ull; acc[oi][j][1] = 0ull; }
        #pragma unroll 2
        for (int c4 = 0; c4 < CH / 4; c4++) {
            const ulonglong2 w1 = ldp(&W2p[c4 * CH + o1]);
            const ulonglong2 w2 = ldp(&W2p[c4 * CH + o2]);
            #pragma unroll
            for (int j = 0; j < 5; j++) {
                #pragma unroll
                for (int p = 0; p < 2; p++) {
                    const ulonglong2 f = ldp(&sH1[p][(wg + 4 * j) * CH + 4 * c4]);
                    ffma2(acc[0][j][p], w1.x, f.x);  ffma2(acc[0][j][p], w1.y, f.y);
                    ffma2(acc[1][j][p], w2.x, f.x);  ffma2(acc[1][j][p], w2.y, f.y);
                }
            }
        }
        const float sca = g2[o1] * bn_rs, boa = b2[o1];
        const float scb = g2[o2] * bn_rs, bob = b2[o2];
        float pma0 = 0.f, pma1 = 0.f, pmb0 = 0.f, pmb1 = 0.f;   // relu floor
        #pragma unroll
        for (int j = 0; j < 5; j++) {
            pma0 = fmaxf(pma0, hsum2(acc[0][j][0]) * sca + boa);
            pma1 = fmaxf(pma1, hsum2(acc[0][j][1]) * sca + boa);
            pmb0 = fmaxf(pmb0, hsum2(acc[1][j][0]) * scb + bob);
            pmb1 = fmaxf(pmb1, hsum2(acc[1][j][1]) * scb + bob);
        }
        sPM[0][wg * CH + o1] = pma0;
        sPM[1][wg * CH + o1] = pma1;
        sPM[0][wg * CH + o2] = pmb0;
        sPM[1][wg * CH + o2] = pmb1;
    }
    __syncthreads();

    {
        const int p = t >> 6, oo = t & 63;
        sFQ[p][oo] = fmaxf(fmaxf(sPM[p][oo], sPM[p][CH + oo]),
                           fmaxf(sPM[p][2 * CH + oo], sPM[p][3 * CH + oo]));
    }
    __syncthreads();

    // ---- q = relu(LN_256(Wq @ fq)) both points ------------------------------------
    {
        float qv0[2], qv1[2];
        #pragma unroll
        for (int r = 0; r < 2; r++) {
            const int oq = t + r * 128;
            ull aA = 0ull, aB = 0ull;
            #pragma unroll
            for (int c4 = 0; c4 < CH / 4; c4++) {
                const ulonglong2 w  = ldp(&Wqp[c4 * 256 + oq]);
                const ulonglong2 fA = ldp(&sFQ[0][4 * c4]);
                const ulonglong2 fB = ldp(&sFQ[1][4 * c4]);
                ffma2(aA, w.x, fA.x);  ffma2(aA, w.y, fA.y);
                ffma2(aB, w.x, fB.x);  ffma2(aB, w.y, fB.y);
            }
            qv0[r] = hsum2(aA);
            qv1[r] = hsum2(aB);
        }
        const float4 ssq = block_sum4_128(
            make_float4(qv0[0] + qv0[1], qv0[0] * qv0[0] + qv0[1] * qv0[1],
                        qv1[0] + qv1[1], qv1[0] * qv1[0] + qv1[1] * qv1[1]),
            sred, sbc);
        const float m0 = ssq.x * (1.f / 256.f);
        const float i0 = rsqrtf(ssq.y * (1.f / 256.f) - m0 * m0 + EPSF);
        const float m1 = ssq.z * (1.f / 256.f);
        const float i1 = rsqrtf(ssq.w * (1.f / 256.f) - m1 * m1 + EPSF);
        #pragma unroll
        for (int r = 0; r < 2; r++) {
            const int oq = t + r * 128;
            const float lw = lnqw[oq], lb = lnqb[oq];
            sQ[0][oq] = fmaxf((qv0[r] - m0) * i0 * lw + lb, 0.f);
            sQ[1][oq] = fmaxf((qv1[r] - m1) * i1 * lw + lb, 0.f);
        }
    }

    // ---- v-raw (pos-only + gather + CV): vd = t&15, k0 = t>>4 ----------------------
    {
        const int vd = t & 15;
        const int k0 = t >> 4;
        ull p0a = 0ull, p0b = 0ull, p0c = 0ull;
        ull p1a = 0ull, p1b = 0ull, p1c = 0ull;
        const bool has2 = (k0 < 4);
        #pragma unroll
        for (int c4 = 0; c4 < 4; c4++) {
            const ulonglong2 w = ldp(&Wvgp[(16 + c4) * DIMV + vd]);
            {
                const ulonglong2 f0 = ldp(&sPos[0][k0 * DIMV + 4 * c4]);
                const ulonglong2 f1 = ldp(&sPos[0][(k0 + 8) * DIMV + 4 * c4]);
                ffma2(p0a, w.x, f0.x);  ffma2(p0a, w.y, f0.y);
                ffma2(p0b, w.x, f1.x);  ffma2(p0b, w.y, f1.y);
                if (has2) {
                    const ulonglong2 f2 = ldp(&sPos[0][(k0 + 16) * DIMV + 4 * c4]);
                    ffma2(p0c, w.x, f2.x);  ffma2(p0c, w.y, f2.y);
                }
            }
            {
                const ulonglong2 f0 = ldp(&sPos[1][k0 * DIMV + 4 * c4]);
                const ulonglong2 f1 = ldp(&sPos[1][(k0 + 8) * DIMV + 4 * c4]);
                ffma2(p1a, w.x, f0.x);  ffma2(p1a, w.y, f0.y);
                ffma2(p1b, w.x, f1.x);  ffma2(p1b, w.y, f1.y);
                if (has2) {
                    const ulonglong2 f2 = ldp(&sPos[1][(k0 + 16) * DIMV + 4 * c4]);
                    ffma2(p1c, w.x, f2.x);  ffma2(p1c, w.y, f2.y);
                }
            }
        }
        const float cv0 = g_C1V[(size_t)bn0 * 80 + 64 + vd];
        const float cv1 = g_C1V[(size_t)(bn0 + 1) * 80 + 64 + vd];
        sV[0][k0 * DIMV + vd]       = hsum2(p0a) + sGP[0][k0 * GPS + GP_GV + vd] + cv0;
        sV[0][(k0 + 8) * DIMV + vd] = hsum2(p0b) + sGP[0][(k0 + 8) * GPS + GP_GV + vd] + cv0;
        sV[1][k0 * DIMV + vd]       = hsum2(p1a) + sGP[1][k0 * GPS + GP_GV + vd] + cv1;
        sV[1][(k0 + 8) * DIMV + vd] = hsum2(p1b) + sGP[1][(k0 + 8) * GPS + GP_GV + vd] + cv1;
        if (has2) {
            sV[0][(k0 + 16) * DIMV + vd] = hsum2(p0c) + sGP[0][(k0 + 16) * GPS + GP_GV + vd] + cv0;
            sV[1][(k0 + 16) * DIMV + vd] = hsum2(p1c) + sGP[1][(k0 + 16) * GPS + GP_GV + vd] + cv1;
        }
    }

    // ---- kk-raw (pos-only + gather): d = t&31, kb = t>>5, 5 k each ------------------
    {
        const int d  = t & 31;
        const int kb = t >> 5;
        ull a0[5], a1[5];
        #pragma unroll
        for (int p = 0; p < 5; p++) { a0[p] = 0ull; a1[p] = 0ull; }
        #pragma unroll
        for (int c4 = 0; c4 < 4; c4++) {
            const ulonglong2 w = ldp(&Wkgp[(16 + c4) * DIMK + d]);
            #pragma unroll
            for (int p = 0; p < 5; p++) {
                const ulonglong2 f0 = ldp(&sPos[0][(kb + 4 * p) * DIMV + 4 * c4]);
                ffma2(a0[p], w.x, f0.x);  ffma2(a0[p], w.y, f0.y);
                const ulonglong2 f1 = ldp(&sPos[1][(kb + 4 * p) * DIMV + 4 * c4]);
                ffma2(a1[p], w.x, f1.x);  ffma2(a1[p], w.y, f1.y);
            }
        }
        #pragma unroll
        for (int p = 0; p < 5; p++) {
            const int k = kb + 4 * p;
            sKK[0][k * DIMK + d] = hsum2(a0[p]) + sGP[0][k * GPS + GP_GK + d];
            sKK[1][k * DIMK + d] = hsum2(a1[p]) + sGP[1][k * GPS + GP_GK + d];
        }
    }
    __syncthreads();

    // ---- LN_16 over v (vectorized, threads 0-39) || softmax (threads 64-127) --------
    if (t < 2 * KNNK) {
        const int p = t / KNNK, row = t - p * KNNK;
        float4 a0 = *(const float4*)&sV[p][row * DIMV + 0];
        float4 a1 = *(const float4*)&sV[p][row * DIMV + 4];
        float4 a2 = *(const float4*)&sV[p][row * DIMV + 8];
        float4 a3 = *(const float4*)&sV[p][row * DIMV + 12];
        const float s  = (a0.x + a0.y + a0.z + a0.w) + (a1.x + a1.y + a1.z + a1.w)
                       + (a2.x + a2.y + a2.z + a2.w) + (a3.x + a3.y + a3.z + a3.w);
        const float s2 = (a0.x * a0.x + a0.y * a0.y + a0.z * a0.z + a0.w * a0.w)
                       + (a1.x * a1.x + a1.y * a1.y + a1.z * a1.z + a1.w * a1.w)
                       + (a2.x * a2.x + a2.y * a2.y + a2.z * a2.z + a2.w * a2.w)
                       + (a3.x * a3.x + a3.y * a3.y + a3.z * a3.z + a3.w * a3.w);
        const float m   = s * (1.f / DIMV);
        const float var = s2 * (1.f / DIMV) - m * m;
        const float inv = rsqrtf(var + EPSF);
        const float4 w0 = *(const float4*)&lnvw[0],  w1 = *(const float4*)&lnvw[4];
        const float4 w2 = *(const float4*)&lnvw[8],  w3 = *(const float4*)&lnvw[12];
        const float4 b0 = *(const float4*)&lnvb[0],  b1v = *(const float4*)&lnvb[4];
        const float4 b2v = *(const float4*)&lnvb[8], b3 = *(const float4*)&lnvb[12];
        a0 = make_float4((a0.x - m) * inv * w0.x + b0.x,  (a0.y - m) * inv * w0.y + b0.y,
                         (a0.z - m) * inv * w0.z + b0.z,  (a0.w - m) * inv * w0.w + b0.w);
        a1 = make_float4((a1.x - m) * inv * w1.x + b1v.x, (a1.y - m) * inv * w1.y + b1v.y,
                         (a1.z - m) * inv * w1.z + b1v.z, (a1.w - m) * inv * w1.w + b1v.w);
        a2 = make_float4((a2.x - m) * inv * w2.x + b2v.x, (a2.y - m) * inv * w2.y + b2v.y,
                         (a2.z - m) * inv * w2.z + b2v.z, (a2.w - m) * inv * w2.w + b2v.w);
        a3 = make_float4((a3.x - m) * inv * w3.x + b3.x,  (a3.y - m) * inv * w3.y + b3.y,
                         (a3.z - m) * inv * w3.z + b3.z,  (a3.w - m) * inv * w3.w + b3.w);
        *(float4*)&sV[p][row * DIMV + 0]  = a0;
        *(float4*)&sV[p][row * DIMV + 4]  = a1;
        *(float4*)&sV[p][row * DIMV + 8]  = a2;
        *(float4*)&sV[p][row * DIMV + 12] = a3;
    } else if (t >= 64) {
        const int idx = t - 64;
        const int p = idx >> 5, d = idx & 31;
        float vals[KNNK];
        float mx = -FLT_MAX;
        #pragma unroll
        for (int k = 0; k < KNNK; k++) {
            vals[k] = sKK[p][k * DIMK + d];
            mx = fmaxf(mx, vals[k]);
        }
        float sum = 0.f;
        #pragma unroll
        for (int k = 0; k < KNNK; k++) {
            vals[k] = expf(vals[k] - mx);
            sum += vals[k];
        }
        const float inv = 1.f / sum;
        #pragma unroll
        for (int k = 0; k < KNNK; k++)
            sKK[p][k * DIMK + d] = vals[k] * inv;
    }
    __syncthreads();

    // ---- kv: thread = (p, d), register accumulators, store transposed ---------------
    if (t < 64) {
        const int p = t >> 5, d = t & 31;
        float acc[DIMV];
        #pragma unroll
        for (int vd = 0; vd < DIMV; vd++) acc[vd] = 0.f;
        #pragma unroll
        for (int k = 0; k < KNNK; k++) {
            const float kkv = sKK[p][k * DIMK + d];
            const float4 v0 = *(const float4*)&sV[p][k * DIMV + 0];
            const float4 v1 = *(const float4*)&sV[p][k * DIMV + 4];
            const float4 v2 = *(const float4*)&sV[p][k * DIMV + 8];
            const float4 v3 = *(const float4*)&sV[p][k * DIMV + 12];
            acc[0]  += kkv * v0.x;  acc[1]  += kkv * v0.y;
            acc[2]  += kkv * v0.z;  acc[3]  += kkv * v0.w;
            acc[4]  += kkv * v1.x;  acc[5]  += kkv * v1.y;
            acc[6]  += kkv * v1.z;  acc[7]  += kkv * v1.w;
            acc[8]  += kkv * v2.x;  acc[9]  += kkv * v2.y;
            acc[10] += kkv * v2.z;  acc[11] += kkv * v2.w;
            acc[12] += kkv * v3.x;  acc[13] += kkv * v3.y;
            acc[14] += kkv * v3.z;  acc[15] += kkv * v3.w;
        }
        #pragma unroll
        for (int vd = 0; vd < DIMV; vd++)
            sKVT[p][vd * DIMK + d] = acc[vd];
    }
    __syncthreads();

    // ---- out = LN_128(q @ kvT) both points, float4 dots, write transposed -------------
    {
        const int h = t >> 4, vd = t & 15;
        float acc0 = 0.f, acc1 = 0.f;
        #pragma unroll
        for (int d4 = 0; d4 < DIMK / 4; d4++) {
            const float4 q0 = *(const float4*)&sQ[0][h * DIMK + 4 * d4];
            const float4 k0 = *(const float4*)&sKVT[0][vd * DIMK + 4 * d4];
            acc0 += q0.x * k0.x + q0.y * k0.y + q0.z * k0.z + q0.w * k0.w;
            const float4 q1 = *(const float4*)&sQ[1][h * DIMK + 4 * d4];
            const float4 k1 = *(const float4*)&sKVT[1][vd * DIMK + 4 * d4];
            acc1 += q1.x * k1.x + q1.y * k1.y + q1.z * k1.z + q1.w * k1.w;
        }
        const float4 ssq = block_sum4_128(
            make_float4(acc0, acc0 * acc0, acc1, acc1 * acc1), sred, sbc);
        const float m0 = ssq.x * (1.f / COUT);
        const float i0 = rsqrtf(ssq.y * (1.f / COUT) - m0 * m0 + EPSF);
        const float m1 = ssq.z * (1.f / COUT);
        const float i1 = rsqrtf(ssq.w * (1.f / COUT) - m1 * m1 + EPSF);
        const float lw = lnow[t], lb = lnob[t];
        float* op = out + XYZ_TOT + ((size_t)b * COUT + t) * NN + n0;
        op[0] = (acc0 - m0) * i0 * lw + lb;
        op[1] = (acc1 - m1) * i1 * lw + lb;
    }
}

// ---------------------------------------------------------------------------
// launch
// ---------------------------------------------------------------------------
extern "C" void kernel_launch(void* const* d_in, const int* in_sizes, int n_in,
                              void* d_out, int out_size)
{
    const float* x    = (const float*)d_in[0];
    const float* Wh   = (const float*)d_in[1];
    const float* W1   = (const float*)d_in[2];
    const float* g1   = (const float*)d_in[3];
    const float* b1   = (const float*)d_in[4];
    const float* W2   = (const float*)d_in[5];
    const float* g2   = (const float*)d_in[6];
    const float* b2   = (const float*)d_in[7];
    const float* Wq   = (const float*)d_in[8];
    const float* lnqw = (const float*)d_in[9];
    const float* lnqb = (const float*)d_in[10];
    const float* Wv   = (const float*)d_in[11];
    const float* lnvw = (const float*)d_in[12];
    const float* lnvb = (const float*)d_in[13];
    const float* Wk   = (const float*)d_in[14];
    const float* lnow = (const float*)d_in[15];
    const float* lnob = (const float*)d_in[16];
    float* out = (float*)d_out;

    const int pack_total = (CR/4)*CH + (CFE/4)*CH + (CH/4)*CH + (CH/4)*NHEAD*DIMK
                         + (CR/4)*DIMV + (CFE/4)*DIMV + (CR/4)*DIMK;
    pack_weights<<<(pack_total + 127) / 128, 128>>>(W1, W2, Wq, Wv, Wk);

    precompute_points<<<BB * NN, 128>>>(x);

    const int knn_smem = 4 * NN * (int)sizeof(float);  // 32 KB
    cudaFuncSetAttribute(knn_kernel,
                         cudaFuncAttributeMaxDynamicSharedMemorySize, knn_smem);
    knn_kernel<<<BB * (NN / 8), 256, knn_smem>>>();

    fused_kernel<<<BB * NN / 2, 128>>>(Wh,
                                       g1, b1, g2, b2,
                                       lnqw, lnqb, lnvw, lnvb,
                                       lnow, lnob,
                                       out);
}